// round 15
// baseline (speedup 1.0000x reference)
#include <cuda_runtime.h>
#include <cuda_bf16.h>
#include <math.h>
#include <cstdint>

#define BB 8192
#define DD 1024
#define INV_TEMP (1.0f / 0.07f)

// ---- scratch (device globals; no allocation allowed) ----
__device__ float g_Z[BB];
__device__ float g_Sp[BB];
__device__ float g_dotM[BB];
__device__ float g_mask[BB];          // 1.0f if machine (label==0)
__device__ int   g_done;
__device__ __nv_bfloat16 g_Ebf[(size_t)BB * DD];   // bf16 copy of embeddings

// ======================= helpers =======================
__device__ __forceinline__ uint32_t smem_u32(const void* p) {
    return (uint32_t)__cvta_generic_to_shared(p);
}
#define SWZ(o) ((o) ^ (((o) >> 3) & 0x70))

__device__ __forceinline__ void cp_async16(uint32_t dst, const void* src) {
    asm volatile("cp.async.cg.shared.global [%0], [%1], 16;"
                 :: "r"(dst), "l"(src) : "memory");
}
__device__ __forceinline__ void cp_commit() {
    asm volatile("cp.async.commit_group;" ::: "memory");
}
template <int N>
__device__ __forceinline__ void cp_wait() {
    asm volatile("cp.async.wait_group %0;" :: "n"(N) : "memory");
}
__device__ __forceinline__ void ldsm_x4(uint32_t* r, uint32_t addr) {
    asm volatile("ldmatrix.sync.aligned.m8n8.x4.shared.b16 {%0,%1,%2,%3}, [%4];"
                 : "=r"(r[0]), "=r"(r[1]), "=r"(r[2]), "=r"(r[3]) : "r"(addr));
}
__device__ __forceinline__ void mma_bf16(float* d, const uint32_t* a,
                                         uint32_t b0, uint32_t b1) {
    asm volatile(
        "mma.sync.aligned.m16n8k16.row.col.f32.bf16.bf16.f32 "
        "{%0,%1,%2,%3}, {%4,%5,%6,%7}, {%8,%9}, {%0,%1,%2,%3};"
        : "+f"(d[0]), "+f"(d[1]), "+f"(d[2]), "+f"(d[3])
        : "r"(a[0]), "r"(a[1]), "r"(a[2]), "r"(a[3]), "r"(b0), "r"(b1));
}

// ======================= row stats: warp-per-row (unit-norm shortcut) ===========
// embeddings and center are exactly unit-norm, so dist = sqrt(2 - 2*dot).
// 4 independent accumulators break the FMA dependency chain.
__global__ void row_stats_kernel(const float* __restrict__ E,
                                 const float* __restrict__ c,
                                 const int* __restrict__ labels,
                                 float* __restrict__ out,
                                 int dist_off) {
    const int warp = threadIdx.x >> 5;
    const int lane = threadIdx.x & 31;
    const int i = blockIdx.x * 8 + warp;
    const float4* e4 = (const float4*)(E + (size_t)i * DD);
    const float4* c4 = (const float4*)c;

    float d0 = 0.f, d1 = 0.f, d2 = 0.f, d3 = 0.f;
    #pragma unroll
    for (int u = 0; u < 8; ++u) {
        const int k = lane + u * 32;
        float4 e = e4[k];
        float4 cc = c4[k];
        d0 += e.x * cc.x;
        d1 += e.y * cc.y;
        d2 += e.z * cc.z;
        d3 += e.w * cc.w;
        __nv_bfloat162 lo = __floats2bfloat162_rn(e.x, e.y);
        __nv_bfloat162 hi = __floats2bfloat162_rn(e.z, e.w);
        __nv_bfloat162* dst = (__nv_bfloat162*)(g_Ebf + (size_t)i * DD + k * 4);
        dst[0] = lo; dst[1] = hi;
    }
    float dc = (d0 + d1) + (d2 + d3);
    #pragma unroll
    for (int o = 16; o > 0; o >>= 1)
        dc += __shfl_down_sync(0xffffffffu, dc, o);

    if (lane == 0) {
        float dist = sqrtf(fmaxf(2.0f - 2.0f * dc, 0.0f));
        out[dist_off + i] = dist;
        g_Sp[i]   = dc * INV_TEMP;
        g_mask[i] = (labels[i] == 0) ? 1.0f : 0.0f;
        g_Z[i]    = 0.0f;
        g_dotM[i] = 0.0f;
        if (i == 0) g_done = 0;
    }
}

// ======================= HMMA GEMM + exp-sum + masked dot-sum + finalize ==========
// CTA tile 128x128, 128 threads (2x2 warp grid, 64x64 warp tiles), 2 CTAs/SM,
// 3-stage cp.async pipeline. Upper-triangle tiles (2080, linearized).
// Diagonal tiles: B == A (B loads skipped; ldmatrix reads A region).
// Last finished CTA computes the final loss scalars (last-block-done).
#define BK 64
#define NCHUNK (DD / BK)           // 16
#define NSTG 3
#define TILE_KB 16384              // 128 rows x 128 B
#define STAGE_BYTES (2 * TILE_KB)  // A + B = 32 KB
#define SMEM_TOTAL (NSTG * STAGE_BYTES)
#define NTILE 64                   // 8192/128
#define TOTTILES 2080

__global__ void __launch_bounds__(128, 2)
gemm_expsum_kernel(const int* __restrict__ labels,
                   const float* __restrict__ dist,
                   const float* __restrict__ rm_p,
                   const float* __restrict__ rh_p,
                   float* __restrict__ out) {
    // linear upper-triangle decode: idx -> (ti, tj), tj >= ti
    const int idx = blockIdx.x;
    int ti = (int)(63.9999f - sqrtf(fmaxf(4095.9f - 2.0f * idx + 0.25f, 0.0f)));
    while (ti > 0 && idx < ti * NTILE - (ti * (ti - 1)) / 2) --ti;
    while (idx >= (ti + 1) * NTILE - ((ti + 1) * ti) / 2) ++ti;
    const int tj = ti + (idx - (ti * NTILE - (ti * (ti - 1)) / 2));
    const bool isdiag = (ti == tj);
    const int ib = ti * 128;
    const int jb = tj * 128;
    const uint32_t bofs = isdiag ? 0u : (uint32_t)TILE_KB;

    extern __shared__ char smem[];
    const uint32_t sbase = smem_u32(smem);
    const int tid  = threadIdx.x;   // 128
    const int lane = tid & 31;
    const int wid  = tid >> 5;      // 0..3
    const int wm   = wid >> 1;      // row group (64 rows)
    const int wn   = wid & 1;       // col group (64 cols)

    const int lrow = tid >> 3;      // 0..15
    const int lch  = tid & 7;       // 16B chunk in 128B row

    // prologue: stages 0,1
    #pragma unroll
    for (int s = 0; s < NSTG - 1; ++s) {
        const uint32_t aB = sbase + s * STAGE_BYTES;
        const size_t kk = (size_t)s * BK;
        #pragma unroll
        for (int r = 0; r < 8; ++r) {
            const int row = lrow + r * 16;
            const uint32_t off = SWZ(row * 128 + lch * 16);
            cp_async16(aB + off, g_Ebf + (size_t)(ib + row) * DD + kk + lch * 8);
        }
        if (!isdiag) {
            #pragma unroll
            for (int r = 0; r < 8; ++r) {
                const int row = lrow + r * 16;
                const uint32_t off = SWZ(row * 128 + lch * 16);
                cp_async16(aB + TILE_KB + off,
                           g_Ebf + (size_t)(jb + row) * DD + kk + lch * 8);
            }
        }
        cp_commit();
    }

    float acc[4][8][4];
    #pragma unroll
    for (int mt = 0; mt < 4; ++mt)
        #pragma unroll
        for (int nt = 0; nt < 8; ++nt)
            #pragma unroll
            for (int q = 0; q < 4; ++q) acc[mt][nt][q] = 0.0f;

    for (int c = 0; c < NCHUNK; ++c) {
        cp_wait<1>();
        __syncthreads();

        if (c + NSTG - 1 < NCHUNK) {
            const int s = (c + NSTG - 1) % NSTG;
            const uint32_t aB = sbase + s * STAGE_BYTES;
            const size_t kk = (size_t)(c + NSTG - 1) * BK;
            #pragma unroll
            for (int r = 0; r < 8; ++r) {
                const int row = lrow + r * 16;
                const uint32_t off = SWZ(row * 128 + lch * 16);
                cp_async16(aB + off, g_Ebf + (size_t)(ib + row) * DD + kk + lch * 8);
            }
            if (!isdiag) {
                #pragma unroll
                for (int r = 0; r < 8; ++r) {
                    const int row = lrow + r * 16;
                    const uint32_t off = SWZ(row * 128 + lch * 16);
                    cp_async16(aB + TILE_KB + off,
                               g_Ebf + (size_t)(jb + row) * DD + kk + lch * 8);
                }
            }
        }
        cp_commit();

        const uint32_t aB = sbase + (c % NSTG) * STAGE_BYTES;
        const uint32_t bB = aB + bofs;
        #pragma unroll
        for (int kq = 0; kq < 4; ++kq) {   // 4 x k16
            uint32_t b[4][4];
            #pragma unroll
            for (int nq = 0; nq < 4; ++nq) {
                const int row = wn * 64 + nq * 16 + (lane & 7) + ((lane >> 4) << 3);
                const int byc = kq * 32 + ((lane >> 3) & 1) * 16;
                ldsm_x4(b[nq], bB + SWZ(row * 128 + byc));
            }
            #pragma unroll
            for (int mt = 0; mt < 4; ++mt) {
                uint32_t a[4];
                const int row = wm * 64 + mt * 16 + (lane & 15);
                const int byc = kq * 32 + (lane >> 4) * 16;
                ldsm_x4(a, aB + SWZ(row * 128 + byc));
                #pragma unroll
                for (int nt = 0; nt < 8; ++nt)
                    mma_bf16(acc[mt][nt], a,
                             b[nt >> 1][(nt & 1) * 2], b[nt >> 1][(nt & 1) * 2 + 1]);
            }
        }
    }
    __syncthreads();   // all reads done before epilogue reuses stage smem

    // ---------------- epilogue: exp sums + masked dot sums ----------------
    const int r_lo = (lane >> 2);
    const int c_lo = (lane & 3) * 2;

    float mi0[4], mi1[4];
    #pragma unroll
    for (int mt = 0; mt < 4; ++mt) {
        const int gi0 = ib + wm * 64 + mt * 16 + r_lo;
        mi0[mt] = g_mask[gi0];
        mi1[mt] = g_mask[gi0 + 8];
    }
    float mj0[8], mj1[8];
    #pragma unroll
    for (int nt = 0; nt < 8; ++nt) {
        const int gj0 = jb + wn * 64 + nt * 8 + c_lo;
        mj0[nt] = g_mask[gj0];
        mj1[nt] = g_mask[gj0 + 1];
    }

    float rowp[4][2], colp[8][2], rowd[4][2], cold[8][2];
    #pragma unroll
    for (int mt = 0; mt < 4; ++mt) {
        rowp[mt][0] = 0.f; rowp[mt][1] = 0.f;
        rowd[mt][0] = 0.f; rowd[mt][1] = 0.f;
    }
    #pragma unroll
    for (int nt = 0; nt < 8; ++nt) {
        colp[nt][0] = 0.f; colp[nt][1] = 0.f;
        cold[nt][0] = 0.f; cold[nt][1] = 0.f;
    }

    #pragma unroll
    for (int mt = 0; mt < 4; ++mt) {
        const int gi0 = ib + wm * 64 + mt * 16 + r_lo;
        const int gi1 = gi0 + 8;
        #pragma unroll
        for (int nt = 0; nt < 8; ++nt) {
            const int gj0 = jb + wn * 64 + nt * 8 + c_lo;
            const int gj1 = gj0 + 1;
            const float a00 = acc[mt][nt][0], a01 = acc[mt][nt][1];
            const float a10 = acc[mt][nt][2], a11 = acc[mt][nt][3];
            rowd[mt][0] += a00 * mj0[nt] + a01 * mj1[nt];
            rowd[mt][1] += a10 * mj0[nt] + a11 * mj1[nt];
            cold[nt][0] += a00 * mi0[mt] + a10 * mi1[mt];
            cold[nt][1] += a01 * mi0[mt] + a11 * mi1[mt];
            float e00 = __expf(a00 * INV_TEMP);
            float e01 = __expf(a01 * INV_TEMP);
            float e10 = __expf(a10 * INV_TEMP);
            float e11 = __expf(a11 * INV_TEMP);
            if (isdiag) {
                if (gi0 == gj0) e00 = 0.0f;
                if (gi0 == gj1) e01 = 0.0f;
                if (gi1 == gj0) e10 = 0.0f;
                if (gi1 == gj1) e11 = 0.0f;
            }
            rowp[mt][0] += e00 + e01;
            rowp[mt][1] += e10 + e11;
            colp[nt][0] += e00 + e10;
            colp[nt][1] += e01 + e11;
        }
    }

    #pragma unroll
    for (int mt = 0; mt < 4; ++mt)
        #pragma unroll
        for (int h = 0; h < 2; ++h) {
            float v = rowp[mt][h];
            v += __shfl_xor_sync(0xffffffffu, v, 1);
            v += __shfl_xor_sync(0xffffffffu, v, 2);
            rowp[mt][h] = v;
            float w = rowd[mt][h];
            w += __shfl_xor_sync(0xffffffffu, w, 1);
            w += __shfl_xor_sync(0xffffffffu, w, 2);
            rowd[mt][h] = w;
        }
    #pragma unroll
    for (int nt = 0; nt < 8; ++nt)
        #pragma unroll
        for (int j = 0; j < 2; ++j) {
            float v = colp[nt][j];
            v += __shfl_xor_sync(0xffffffffu, v, 4);
            v += __shfl_xor_sync(0xffffffffu, v, 8);
            v += __shfl_xor_sync(0xffffffffu, v, 16);
            colp[nt][j] = v;
            float w = cold[nt][j];
            w += __shfl_xor_sync(0xffffffffu, w, 4);
            w += __shfl_xor_sync(0xffffffffu, w, 8);
            w += __shfl_xor_sync(0xffffffffu, w, 16);
            cold[nt][j] = w;
        }

    float* rowred  = (float*)smem;               // [128][2]
    float* colred  = (float*)(smem + 1024);      // [128][2]
    float* rowdred = (float*)(smem + 2048);      // [128][2]
    float* coldred = (float*)(smem + 3072);      // [128][2]

    if ((lane & 3) == 0) {
        #pragma unroll
        for (int mt = 0; mt < 4; ++mt)
            #pragma unroll
            for (int h = 0; h < 2; ++h) {
                const int row = wm * 64 + mt * 16 + r_lo + 8 * h;
                rowred[row * 2 + wn]  = rowp[mt][h];
                rowdred[row * 2 + wn] = rowd[mt][h];
            }
    }
    if (lane < 4) {
        #pragma unroll
        for (int nt = 0; nt < 8; ++nt)
            #pragma unroll
            for (int j = 0; j < 2; ++j) {
                const int col = wn * 64 + nt * 8 + lane * 2 + j;
                colred[col * 2 + wm]  = colp[nt][j];
                coldred[col * 2 + wm] = cold[nt][j];
            }
    }
    __syncthreads();

    atomicAdd(&g_Z[ib + tid],    rowred[tid * 2]  + rowred[tid * 2 + 1]);
    atomicAdd(&g_dotM[ib + tid], rowdred[tid * 2] + rowdred[tid * 2 + 1]);
    if (!isdiag) {
        atomicAdd(&g_Z[jb + tid],    colred[tid * 2]  + colred[tid * 2 + 1]);
        atomicAdd(&g_dotM[jb + tid], coldred[tid * 2] + coldred[tid * 2 + 1]);
    }

    // ---------------- last-block-done finalize ----------------
    __shared__ int s_last;
    __threadfence();
    if (tid == 0)
        s_last = (atomicAdd(&g_done, 1) == TOTTILES - 1) ? 1 : 0;
    __syncthreads();
    if (!s_last) return;

    // |Sp| <= 1/TEMP so exp(Sp) <= 1.6e6: fp32-safe, no max-subtraction.
    // ||e_i||^2 == 1 exactly, so pos uses (dotM - 1).
    const float rm = rm_p[0];
    const float rh = rh_p[0];
    float sumexp = 0.f, msp = 0.f, mlse = 0.f, mpos = 0.f, shm = 0.f, shh = 0.f;
    int nm = 0;
    for (int i = tid; i < BB; i += 128) {
        const float sp = g_Sp[i];
        const float ep = __expf(sp);
        sumexp += ep;
        const float d = dist[i];
        if (labels[i] == 0) {
            ++nm;
            mlse += logf(g_Z[i] + ep);
            mpos += (g_dotM[i] - 1.0f) * INV_TEMP + sp;
            msp  += sp;
            float r = fmaxf(d - rm, 0.0f);
            shm += r * r;
        } else {
            float r = fmaxf(rh - d, 0.0f);
            shh += r * r;
        }
    }
    // block reduction in (now dead) stage smem
    float* red = (float*)smem;
    int*   redi = (int*)(smem + 6 * 128 * 4);
    red[tid]           = sumexp;
    red[128 + tid]     = msp;
    red[256 + tid]     = mlse;
    red[384 + tid]     = mpos;
    red[512 + tid]     = shm;
    red[640 + tid]     = shh;
    redi[tid]          = nm;
    __syncthreads();
    for (int o = 64; o > 0; o >>= 1) {
        if (tid < o) {
            red[tid]       += red[tid + o];
            red[128 + tid] += red[128 + tid + o];
            red[256 + tid] += red[256 + tid + o];
            red[384 + tid] += red[384 + tid + o];
            red[512 + tid] += red[512 + tid + o];
            red[640 + tid] += red[640 + tid + o];
            redi[tid]      += redi[tid + o];
        }
        __syncthreads();
    }
    if (tid == 0) {
        const int nm_i = redi[0];
        const int nh_i = BB - nm_i;
        const float nm_den = fmaxf((float)nm_i, 1.0f);
        const float nh_den = fmaxf((float)nh_i, 1.0f);

        float con_sum = red[256] - red[384] / nm_den;
        float lse_p = logf(red[0]);
        float proto_loss = lse_p - red[128] / nm_den;
        float loss_con = (con_sum + proto_loss) / fmaxf((float)(nm_i + 1), 1.0f);
        if (!(nm_i > 0 && nh_i > 0)) loss_con = 0.0f;
        float loss_m = red[512] / nm_den;
        float loss_h = red[640] / nh_den;
        float loss_shell = loss_m + loss_h;
        out[0] = loss_shell + loss_con;
        out[1] = loss_shell;
        out[2] = loss_m;
        out[3] = loss_h;
        out[4] = loss_con;
    }
}

extern "C" void kernel_launch(void* const* d_in, const int* in_sizes, int n_in,
                              void* d_out, int out_size) {
    const float* E      = (const float*)d_in[0];
    const float* center = (const float*)d_in[1];
    const float* rm     = (const float*)d_in[2];
    const float* rh     = (const float*)d_in[3];
    const int*   labels = (const int*)d_in[4];
    float* out = (float*)d_out;

    const int dist_off = out_size - BB;

    cudaFuncSetAttribute(gemm_expsum_kernel,
                         cudaFuncAttributeMaxDynamicSharedMemorySize, SMEM_TOTAL);

    row_stats_kernel<<<BB / 8, 256>>>(E, center, labels, out, dist_off);
    gemm_expsum_kernel<<<TOTTILES, 128, SMEM_TOTAL>>>(labels, out + dist_off,
                                                      rm, rh, out);
}

// round 16
// speedup vs baseline: 1.4783x; 1.4783x over previous
#include <cuda_runtime.h>
#include <cuda_bf16.h>
#include <math.h>
#include <cstdint>

#define BB 8192
#define DD 1024
#define INV_TEMP (1.0f / 0.07f)

// ---- scratch (device globals; no allocation allowed) ----
__device__ float g_Z[BB];
__device__ float g_Sp[BB];
__device__ float g_dotM[BB];
__device__ float g_mask[BB];          // 1.0f if machine (label==0)
__device__ float g_shell_m;
__device__ float g_shell_h;
__device__ int   g_nm;
__device__ float g_sumexp_p;
__device__ float g_sum_m_sp;
__device__ float g_sum_m_lse;
__device__ float g_sum_m_pos;
__device__ int   g_done;
__device__ __nv_bfloat16 g_Ebf[(size_t)BB * DD];   // bf16 copy of embeddings

// ======================= helpers =======================
__device__ __forceinline__ uint32_t smem_u32(const void* p) {
    return (uint32_t)__cvta_generic_to_shared(p);
}
#define SWZ(o) ((o) ^ (((o) >> 3) & 0x70))

__device__ __forceinline__ void cp_async16(uint32_t dst, const void* src) {
    asm volatile("cp.async.cg.shared.global [%0], [%1], 16;"
                 :: "r"(dst), "l"(src) : "memory");
}
__device__ __forceinline__ void cp_commit() {
    asm volatile("cp.async.commit_group;" ::: "memory");
}
template <int N>
__device__ __forceinline__ void cp_wait() {
    asm volatile("cp.async.wait_group %0;" :: "n"(N) : "memory");
}
__device__ __forceinline__ void ldsm_x4(uint32_t* r, uint32_t addr) {
    asm volatile("ldmatrix.sync.aligned.m8n8.x4.shared.b16 {%0,%1,%2,%3}, [%4];"
                 : "=r"(r[0]), "=r"(r[1]), "=r"(r[2]), "=r"(r[3]) : "r"(addr));
}
__device__ __forceinline__ void mma_bf16(float* d, const uint32_t* a,
                                         uint32_t b0, uint32_t b1) {
    asm volatile(
        "mma.sync.aligned.m16n8k16.row.col.f32.bf16.bf16.f32 "
        "{%0,%1,%2,%3}, {%4,%5,%6,%7}, {%8,%9}, {%0,%1,%2,%3};"
        : "+f"(d[0]), "+f"(d[1]), "+f"(d[2]), "+f"(d[3])
        : "r"(a[0]), "r"(a[1]), "r"(a[2]), "r"(a[3]), "r"(b0), "r"(b1));
}

// ======================= row stats: warp-per-row (unit-norm shortcut) ===========
// embeddings and center are exactly unit-norm, so dist = sqrt(2 - 2*dot).
// 4 independent accumulators break the FMA dependency chain.
// E fp32 is read once -> streaming loads (evict-first) keep L2 for g_Ebf.
__global__ void row_stats_kernel(const float* __restrict__ E,
                                 const float* __restrict__ c,
                                 const int* __restrict__ labels,
                                 float* __restrict__ out,
                                 int dist_off) {
    const int warp = threadIdx.x >> 5;
    const int lane = threadIdx.x & 31;
    const int i = blockIdx.x * 8 + warp;
    const float4* e4 = (const float4*)(E + (size_t)i * DD);
    const float4* c4 = (const float4*)c;

    float d0 = 0.f, d1 = 0.f, d2 = 0.f, d3 = 0.f;
    #pragma unroll
    for (int u = 0; u < 8; ++u) {
        const int k = lane + u * 32;
        float4 e = __ldcs(&e4[k]);
        float4 cc = c4[k];
        d0 += e.x * cc.x;
        d1 += e.y * cc.y;
        d2 += e.z * cc.z;
        d3 += e.w * cc.w;
        __nv_bfloat162 lo = __floats2bfloat162_rn(e.x, e.y);
        __nv_bfloat162 hi = __floats2bfloat162_rn(e.z, e.w);
        __nv_bfloat162* dst = (__nv_bfloat162*)(g_Ebf + (size_t)i * DD + k * 4);
        dst[0] = lo; dst[1] = hi;
    }
    float dc = (d0 + d1) + (d2 + d3);
    #pragma unroll
    for (int o = 16; o > 0; o >>= 1)
        dc += __shfl_down_sync(0xffffffffu, dc, o);

    if (lane == 0) {
        float dist = sqrtf(fmaxf(2.0f - 2.0f * dc, 0.0f));
        out[dist_off + i] = dist;
        g_Sp[i]   = dc * INV_TEMP;
        g_mask[i] = (labels[i] == 0) ? 1.0f : 0.0f;
        g_Z[i]    = 0.0f;
        g_dotM[i] = 0.0f;
        if (i == 0) {
            g_shell_m = 0.0f; g_shell_h = 0.0f; g_nm = 0;
            g_sumexp_p = 0.0f; g_sum_m_sp = 0.0f;
            g_sum_m_lse = 0.0f; g_sum_m_pos = 0.0f;
            g_done = 0;
        }
    }
}

// ======================= HMMA GEMM + exp-sum + masked dot-sum =======================
// CTA tile 128x128, 128 threads (2x2 warp grid, 64x64 warp tiles), 2 CTAs/SM,
// 3-stage cp.async pipeline. Upper-triangle tiles (2080, linearized).
// Diagonal tiles: B == A (B loads skipped; ldmatrix reads A region).
#define BK 64
#define NCHUNK (DD / BK)           // 16
#define NSTG 3
#define TILE_KB 16384              // 128 rows x 128 B
#define STAGE_BYTES (2 * TILE_KB)  // A + B = 32 KB
#define SMEM_TOTAL (NSTG * STAGE_BYTES)
#define NTILE 64                   // 8192/128

__global__ void __launch_bounds__(128, 2)
gemm_expsum_kernel() {
    // linear upper-triangle decode: idx -> (ti, tj), tj >= ti
    const int idx = blockIdx.x;
    int ti = (int)(63.9999f - sqrtf(fmaxf(4095.9f - 2.0f * idx + 0.25f, 0.0f)));
    while (ti > 0 && idx < ti * NTILE - (ti * (ti - 1)) / 2) --ti;
    while (idx >= (ti + 1) * NTILE - ((ti + 1) * ti) / 2) ++ti;
    const int tj = ti + (idx - (ti * NTILE - (ti * (ti - 1)) / 2));
    const bool isdiag = (ti == tj);
    const int ib = ti * 128;
    const int jb = tj * 128;
    const uint32_t bofs = isdiag ? 0u : (uint32_t)TILE_KB;

    extern __shared__ char smem[];
    const uint32_t sbase = smem_u32(smem);
    const int tid  = threadIdx.x;   // 128
    const int lane = tid & 31;
    const int wid  = tid >> 5;      // 0..3
    const int wm   = wid >> 1;      // row group (64 rows)
    const int wn   = wid & 1;       // col group (64 cols)

    const int lrow = tid >> 3;      // 0..15
    const int lch  = tid & 7;       // 16B chunk in 128B row

    // prologue: stages 0,1
    #pragma unroll
    for (int s = 0; s < NSTG - 1; ++s) {
        const uint32_t aB = sbase + s * STAGE_BYTES;
        const size_t kk = (size_t)s * BK;
        #pragma unroll
        for (int r = 0; r < 8; ++r) {
            const int row = lrow + r * 16;
            const uint32_t off = SWZ(row * 128 + lch * 16);
            cp_async16(aB + off, g_Ebf + (size_t)(ib + row) * DD + kk + lch * 8);
        }
        if (!isdiag) {
            #pragma unroll
            for (int r = 0; r < 8; ++r) {
                const int row = lrow + r * 16;
                const uint32_t off = SWZ(row * 128 + lch * 16);
                cp_async16(aB + TILE_KB + off,
                           g_Ebf + (size_t)(jb + row) * DD + kk + lch * 8);
            }
        }
        cp_commit();
    }

    float acc[4][8][4];
    #pragma unroll
    for (int mt = 0; mt < 4; ++mt)
        #pragma unroll
        for (int nt = 0; nt < 8; ++nt)
            #pragma unroll
            for (int q = 0; q < 4; ++q) acc[mt][nt][q] = 0.0f;

    for (int c = 0; c < NCHUNK; ++c) {
        cp_wait<1>();
        __syncthreads();

        if (c + NSTG - 1 < NCHUNK) {
            const int s = (c + NSTG - 1) % NSTG;
            const uint32_t aB = sbase + s * STAGE_BYTES;
            const size_t kk = (size_t)(c + NSTG - 1) * BK;
            #pragma unroll
            for (int r = 0; r < 8; ++r) {
                const int row = lrow + r * 16;
                const uint32_t off = SWZ(row * 128 + lch * 16);
                cp_async16(aB + off, g_Ebf + (size_t)(ib + row) * DD + kk + lch * 8);
            }
            if (!isdiag) {
                #pragma unroll
                for (int r = 0; r < 8; ++r) {
                    const int row = lrow + r * 16;
                    const uint32_t off = SWZ(row * 128 + lch * 16);
                    cp_async16(aB + TILE_KB + off,
                               g_Ebf + (size_t)(jb + row) * DD + kk + lch * 8);
                }
            }
        }
        cp_commit();

        const uint32_t aB = sbase + (c % NSTG) * STAGE_BYTES;
        const uint32_t bB = aB + bofs;
        #pragma unroll
        for (int kq = 0; kq < 4; ++kq) {   // 4 x k16
            uint32_t b[4][4];
            #pragma unroll
            for (int nq = 0; nq < 4; ++nq) {
                const int row = wn * 64 + nq * 16 + (lane & 7) + ((lane >> 4) << 3);
                const int byc = kq * 32 + ((lane >> 3) & 1) * 16;
                ldsm_x4(b[nq], bB + SWZ(row * 128 + byc));
            }
            #pragma unroll
            for (int mt = 0; mt < 4; ++mt) {
                uint32_t a[4];
                const int row = wm * 64 + mt * 16 + (lane & 15);
                const int byc = kq * 32 + (lane >> 4) * 16;
                ldsm_x4(a, aB + SWZ(row * 128 + byc));
                #pragma unroll
                for (int nt = 0; nt < 8; ++nt)
                    mma_bf16(acc[mt][nt], a,
                             b[nt >> 1][(nt & 1) * 2], b[nt >> 1][(nt & 1) * 2 + 1]);
            }
        }
    }
    __syncthreads();   // all reads done before epilogue reuses stage smem

    // ---------------- epilogue: exp sums + masked dot sums ----------------
    const int r_lo = (lane >> 2);
    const int c_lo = (lane & 3) * 2;

    float mi0[4], mi1[4];
    #pragma unroll
    for (int mt = 0; mt < 4; ++mt) {
        const int gi0 = ib + wm * 64 + mt * 16 + r_lo;
        mi0[mt] = g_mask[gi0];
        mi1[mt] = g_mask[gi0 + 8];
    }
    float mj0[8], mj1[8];
    #pragma unroll
    for (int nt = 0; nt < 8; ++nt) {
        const int gj0 = jb + wn * 64 + nt * 8 + c_lo;
        mj0[nt] = g_mask[gj0];
        mj1[nt] = g_mask[gj0 + 1];
    }

    float rowp[4][2], colp[8][2], rowd[4][2], cold[8][2];
    #pragma unroll
    for (int mt = 0; mt < 4; ++mt) {
        rowp[mt][0] = 0.f; rowp[mt][1] = 0.f;
        rowd[mt][0] = 0.f; rowd[mt][1] = 0.f;
    }
    #pragma unroll
    for (int nt = 0; nt < 8; ++nt) {
        colp[nt][0] = 0.f; colp[nt][1] = 0.f;
        cold[nt][0] = 0.f; cold[nt][1] = 0.f;
    }

    #pragma unroll
    for (int mt = 0; mt < 4; ++mt) {
        const int gi0 = ib + wm * 64 + mt * 16 + r_lo;
        const int gi1 = gi0 + 8;
        #pragma unroll
        for (int nt = 0; nt < 8; ++nt) {
            const int gj0 = jb + wn * 64 + nt * 8 + c_lo;
            const int gj1 = gj0 + 1;
            const float a00 = acc[mt][nt][0], a01 = acc[mt][nt][1];
            const float a10 = acc[mt][nt][2], a11 = acc[mt][nt][3];
            rowd[mt][0] += a00 * mj0[nt] + a01 * mj1[nt];
            rowd[mt][1] += a10 * mj0[nt] + a11 * mj1[nt];
            cold[nt][0] += a00 * mi0[mt] + a10 * mi1[mt];
            cold[nt][1] += a01 * mi0[mt] + a11 * mi1[mt];
            float e00 = __expf(a00 * INV_TEMP);
            float e01 = __expf(a01 * INV_TEMP);
            float e10 = __expf(a10 * INV_TEMP);
            float e11 = __expf(a11 * INV_TEMP);
            if (isdiag) {
                if (gi0 == gj0) e00 = 0.0f;
                if (gi0 == gj1) e01 = 0.0f;
                if (gi1 == gj0) e10 = 0.0f;
                if (gi1 == gj1) e11 = 0.0f;
            }
            rowp[mt][0] += e00 + e01;
            rowp[mt][1] += e10 + e11;
            colp[nt][0] += e00 + e10;
            colp[nt][1] += e01 + e11;
        }
    }

    #pragma unroll
    for (int mt = 0; mt < 4; ++mt)
        #pragma unroll
        for (int h = 0; h < 2; ++h) {
            float v = rowp[mt][h];
            v += __shfl_xor_sync(0xffffffffu, v, 1);
            v += __shfl_xor_sync(0xffffffffu, v, 2);
            rowp[mt][h] = v;
            float w = rowd[mt][h];
            w += __shfl_xor_sync(0xffffffffu, w, 1);
            w += __shfl_xor_sync(0xffffffffu, w, 2);
            rowd[mt][h] = w;
        }
    #pragma unroll
    for (int nt = 0; nt < 8; ++nt)
        #pragma unroll
        for (int j = 0; j < 2; ++j) {
            float v = colp[nt][j];
            v += __shfl_xor_sync(0xffffffffu, v, 4);
            v += __shfl_xor_sync(0xffffffffu, v, 8);
            v += __shfl_xor_sync(0xffffffffu, v, 16);
            colp[nt][j] = v;
            float w = cold[nt][j];
            w += __shfl_xor_sync(0xffffffffu, w, 4);
            w += __shfl_xor_sync(0xffffffffu, w, 8);
            w += __shfl_xor_sync(0xffffffffu, w, 16);
            cold[nt][j] = w;
        }

    float* rowred  = (float*)smem;               // [128][2]
    float* colred  = (float*)(smem + 1024);      // [128][2]
    float* rowdred = (float*)(smem + 2048);      // [128][2]
    float* coldred = (float*)(smem + 3072);      // [128][2]

    if ((lane & 3) == 0) {
        #pragma unroll
        for (int mt = 0; mt < 4; ++mt)
            #pragma unroll
            for (int h = 0; h < 2; ++h) {
                const int row = wm * 64 + mt * 16 + r_lo + 8 * h;
                rowred[row * 2 + wn]  = rowp[mt][h];
                rowdred[row * 2 + wn] = rowd[mt][h];
            }
    }
    if (lane < 4) {
        #pragma unroll
        for (int nt = 0; nt < 8; ++nt)
            #pragma unroll
            for (int j = 0; j < 2; ++j) {
                const int col = wn * 64 + nt * 8 + lane * 2 + j;
                colred[col * 2 + wm]  = colp[nt][j];
                coldred[col * 2 + wm] = cold[nt][j];
            }
    }
    __syncthreads();

    atomicAdd(&g_Z[ib + tid],    rowred[tid * 2]  + rowred[tid * 2 + 1]);
    atomicAdd(&g_dotM[ib + tid], rowdred[tid * 2] + rowdred[tid * 2 + 1]);
    if (!isdiag) {
        atomicAdd(&g_Z[jb + tid],    colred[tid * 2]  + colred[tid * 2 + 1]);
        atomicAdd(&g_dotM[jb + tid], coldred[tid * 2] + coldred[tid * 2 + 1]);
    }
}

// ======================= finalize (single kernel, last-block-done) ==============
// |Sp| <= 1/TEMP so exp(Sp) <= 1.6e6: fp32-safe, no max-subtraction.
// ||e_i||^2 == 1 exactly (unit-norm), so pos uses (dotM - 1).
#define FIN_BLOCKS (BB / 256)   // 32

__global__ void finalize_kernel(const int* __restrict__ labels,
                                const float* __restrict__ dist,
                                const float* __restrict__ rm_p,
                                const float* __restrict__ rh_p,
                                float* __restrict__ out) {
    const int i = blockIdx.x * 256 + threadIdx.x;
    const int t = threadIdx.x;

    const float sp = g_Sp[i];
    const float ep = __expf(sp);
    const bool m = (labels[i] == 0);
    const float d = dist[i];

    float lse = 0.0f, pos = 0.0f, msp = 0.0f, sm = 0.0f, sh2 = 0.0f;
    int cm = 0;
    if (m) {
        lse = logf(g_Z[i] + ep);
        pos = (g_dotM[i] - 1.0f) * INV_TEMP + sp;
        msp = sp;
        cm = 1;
        float r = fmaxf(d - rm_p[0], 0.0f);
        sm = r * r;
    } else {
        float r = fmaxf(rh_p[0] - d, 0.0f);
        sh2 = r * r;
    }

    __shared__ float s[6][256];
    __shared__ int   si[256];
    s[0][t] = ep; s[1][t] = msp; s[2][t] = lse; s[3][t] = pos;
    s[4][t] = sm; s[5][t] = sh2; si[t] = cm;
    __syncthreads();
    for (int o = 128; o > 0; o >>= 1) {
        if (t < o) {
            s[0][t] += s[0][t + o]; s[1][t] += s[1][t + o];
            s[2][t] += s[2][t + o]; s[3][t] += s[3][t + o];
            s[4][t] += s[4][t + o]; s[5][t] += s[5][t + o];
            si[t] += si[t + o];
        }
        __syncthreads();
    }
    __shared__ int s_last;
    if (t == 0) {
        atomicAdd(&g_sumexp_p,  s[0][0]);
        atomicAdd(&g_sum_m_sp,  s[1][0]);
        atomicAdd(&g_sum_m_lse, s[2][0]);
        atomicAdd(&g_sum_m_pos, s[3][0]);
        atomicAdd(&g_shell_m,   s[4][0]);
        atomicAdd(&g_shell_h,   s[5][0]);
        atomicAdd(&g_nm,        si[0]);
        __threadfence();
        s_last = (atomicAdd(&g_done, 1) == FIN_BLOCKS - 1) ? 1 : 0;
    }
    __syncthreads();
    if (s_last && t == 0) {
        const int nm_i = g_nm;
        const int nh_i = BB - nm_i;
        const float nm_den = fmaxf((float)nm_i, 1.0f);
        const float nh_den = fmaxf((float)nh_i, 1.0f);

        float con_sum = g_sum_m_lse - g_sum_m_pos / nm_den;
        float lse_p = logf(g_sumexp_p);
        float proto_loss = lse_p - g_sum_m_sp / nm_den;
        float loss_con = (con_sum + proto_loss) / fmaxf((float)(nm_i + 1), 1.0f);
        if (!(nm_i > 0 && nh_i > 0)) loss_con = 0.0f;
        float loss_m = g_shell_m / nm_den;
        float loss_h = g_shell_h / nh_den;
        float loss_shell = loss_m + loss_h;
        out[0] = loss_shell + loss_con;
        out[1] = loss_shell;
        out[2] = loss_m;
        out[3] = loss_h;
        out[4] = loss_con;
    }
}

extern "C" void kernel_launch(void* const* d_in, const int* in_sizes, int n_in,
                              void* d_out, int out_size) {
    const float* E      = (const float*)d_in[0];
    const float* center = (const float*)d_in[1];
    const float* rm     = (const float*)d_in[2];
    const float* rh     = (const float*)d_in[3];
    const int*   labels = (const int*)d_in[4];
    float* out = (float*)d_out;

    const int dist_off = out_size - BB;

    cudaFuncSetAttribute(gemm_expsum_kernel,
                         cudaFuncAttributeMaxDynamicSharedMemorySize, SMEM_TOTAL);

    row_stats_kernel<<<BB / 8, 256>>>(E, center, labels, out, dist_off);
    gemm_expsum_kernel<<<(NTILE * (NTILE + 1)) / 2, 128, SMEM_TOTAL>>>();
    finalize_kernel<<<FIN_BLOCKS, 256>>>(labels, out + dist_off, rm, rh, out);
}

// round 17
// speedup vs baseline: 1.4889x; 1.0072x over previous
#include <cuda_runtime.h>
#include <cuda_bf16.h>
#include <math.h>
#include <cstdint>

#define BB 8192
#define DD 1024
#define INV_TEMP (1.0f / 0.07f)
#define INV_TEMP_LOG2E (1.44269504088896f / 0.07f)   // for exp2f-based exp

// ---- scratch (device globals; no allocation allowed) ----
__device__ float g_Z[BB];
__device__ float g_Sp[BB];
__device__ float g_dotM[BB];
__device__ float g_mask[BB];          // 1.0f if machine (label==0)
__device__ float g_shell_m;
__device__ float g_shell_h;
__device__ int   g_nm;
__device__ float g_sumexp_p;
__device__ float g_sum_m_sp;
__device__ float g_sum_m_lse;
__device__ float g_sum_m_pos;
__device__ int   g_done;
__device__ __nv_bfloat16 g_Ebf[(size_t)BB * DD];   // bf16 copy of embeddings

// ======================= helpers =======================
__device__ __forceinline__ uint32_t smem_u32(const void* p) {
    return (uint32_t)__cvta_generic_to_shared(p);
}
#define SWZ(o) ((o) ^ (((o) >> 3) & 0x70))

__device__ __forceinline__ void cp_async16(uint32_t dst, const void* src) {
    asm volatile("cp.async.cg.shared.global [%0], [%1], 16;"
                 :: "r"(dst), "l"(src) : "memory");
}
__device__ __forceinline__ void cp_commit() {
    asm volatile("cp.async.commit_group;" ::: "memory");
}
template <int N>
__device__ __forceinline__ void cp_wait() {
    asm volatile("cp.async.wait_group %0;" :: "n"(N) : "memory");
}
__device__ __forceinline__ void ldsm_x4(uint32_t* r, uint32_t addr) {
    asm volatile("ldmatrix.sync.aligned.m8n8.x4.shared.b16 {%0,%1,%2,%3}, [%4];"
                 : "=r"(r[0]), "=r"(r[1]), "=r"(r[2]), "=r"(r[3]) : "r"(addr));
}
__device__ __forceinline__ void mma_bf16(float* d, const uint32_t* a,
                                         uint32_t b0, uint32_t b1) {
    asm volatile(
        "mma.sync.aligned.m16n8k16.row.col.f32.bf16.bf16.f32 "
        "{%0,%1,%2,%3}, {%4,%5,%6,%7}, {%8,%9}, {%0,%1,%2,%3};"
        : "+f"(d[0]), "+f"(d[1]), "+f"(d[2]), "+f"(d[3])
        : "r"(a[0]), "r"(a[1]), "r"(a[2]), "r"(a[3]), "r"(b0), "r"(b1));
}

// ======================= row stats: warp-per-row (unit-norm shortcut) ===========
__global__ void row_stats_kernel(const float* __restrict__ E,
                                 const float* __restrict__ c,
                                 const int* __restrict__ labels,
                                 float* __restrict__ out,
                                 int dist_off) {
    const int warp = threadIdx.x >> 5;
    const int lane = threadIdx.x & 31;
    const int i = blockIdx.x * 8 + warp;
    const float4* e4 = (const float4*)(E + (size_t)i * DD);
    const float4* c4 = (const float4*)c;

    float d0 = 0.f, d1 = 0.f, d2 = 0.f, d3 = 0.f;
    #pragma unroll
    for (int u = 0; u < 8; ++u) {
        const int k = lane + u * 32;
        float4 e = __ldcs(&e4[k]);
        float4 cc = c4[k];
        d0 += e.x * cc.x;
        d1 += e.y * cc.y;
        d2 += e.z * cc.z;
        d3 += e.w * cc.w;
        __nv_bfloat162 lo = __floats2bfloat162_rn(e.x, e.y);
        __nv_bfloat162 hi = __floats2bfloat162_rn(e.z, e.w);
        __nv_bfloat162* dst = (__nv_bfloat162*)(g_Ebf + (size_t)i * DD + k * 4);
        dst[0] = lo; dst[1] = hi;
    }
    float dc = (d0 + d1) + (d2 + d3);
    #pragma unroll
    for (int o = 16; o > 0; o >>= 1)
        dc += __shfl_down_sync(0xffffffffu, dc, o);

    if (lane == 0) {
        float dist = sqrtf(fmaxf(2.0f - 2.0f * dc, 0.0f));
        out[dist_off + i] = dist;
        g_Sp[i]   = dc * INV_TEMP;
        g_mask[i] = (labels[i] == 0) ? 1.0f : 0.0f;
        g_Z[i]    = 0.0f;
        g_dotM[i] = 0.0f;
        if (i == 0) {
            g_shell_m = 0.0f; g_shell_h = 0.0f; g_nm = 0;
            g_sumexp_p = 0.0f; g_sum_m_sp = 0.0f;
            g_sum_m_lse = 0.0f; g_sum_m_pos = 0.0f;
            g_done = 0;
        }
    }
}

// ======================= HMMA GEMM + exp-sum + masked dot-sum =======================
// CTA tile 128x128, 128 threads (2x2 warp grid, 64x64 warp tiles), 2 CTAs/SM,
// 3-stage cp.async pipeline. Upper-triangle tiles (2080, linearized).
// Diagonal tiles: B == A (B loads skipped; ldmatrix reads A region).
#define BK 64
#define NCHUNK (DD / BK)           // 16
#define NSTG 3
#define TILE_KB 16384              // 128 rows x 128 B
#define STAGE_BYTES (2 * TILE_KB)  // A + B = 32 KB
#define SMEM_TOTAL (NSTG * STAGE_BYTES)
#define NTILE 64                   // 8192/128

__global__ void __launch_bounds__(128, 2)
gemm_expsum_kernel() {
    // linear upper-triangle decode: idx -> (ti, tj), tj >= ti
    const int idx = blockIdx.x;
    int ti = (int)(63.9999f - sqrtf(fmaxf(4095.9f - 2.0f * idx + 0.25f, 0.0f)));
    while (ti > 0 && idx < ti * NTILE - (ti * (ti - 1)) / 2) --ti;
    while (idx >= (ti + 1) * NTILE - ((ti + 1) * ti) / 2) ++ti;
    const int tj = ti + (idx - (ti * NTILE - (ti * (ti - 1)) / 2));
    const bool isdiag = (ti == tj);
    const int ib = ti * 128;
    const int jb = tj * 128;
    const uint32_t bofs = isdiag ? 0u : (uint32_t)TILE_KB;

    extern __shared__ char smem[];
    const uint32_t sbase = smem_u32(smem);
    const int tid  = threadIdx.x;   // 128
    const int lane = tid & 31;
    const int wid  = tid >> 5;      // 0..3
    const int wm   = wid >> 1;      // row group (64 rows)
    const int wn   = wid & 1;       // col group (64 cols)

    const int lrow = tid >> 3;      // 0..15
    const int lch  = tid & 7;       // 16B chunk in 128B row

    // prologue: stages 0,1
    #pragma unroll
    for (int s = 0; s < NSTG - 1; ++s) {
        const uint32_t aB = sbase + s * STAGE_BYTES;
        const size_t kk = (size_t)s * BK;
        #pragma unroll
        for (int r = 0; r < 8; ++r) {
            const int row = lrow + r * 16;
            const uint32_t off = SWZ(row * 128 + lch * 16);
            cp_async16(aB + off, g_Ebf + (size_t)(ib + row) * DD + kk + lch * 8);
        }
        if (!isdiag) {
            #pragma unroll
            for (int r = 0; r < 8; ++r) {
                const int row = lrow + r * 16;
                const uint32_t off = SWZ(row * 128 + lch * 16);
                cp_async16(aB + TILE_KB + off,
                           g_Ebf + (size_t)(jb + row) * DD + kk + lch * 8);
            }
        }
        cp_commit();
    }

    float acc[4][8][4];
    #pragma unroll
    for (int mt = 0; mt < 4; ++mt)
        #pragma unroll
        for (int nt = 0; nt < 8; ++nt)
            #pragma unroll
            for (int q = 0; q < 4; ++q) acc[mt][nt][q] = 0.0f;

    for (int c = 0; c < NCHUNK; ++c) {
        cp_wait<1>();
        __syncthreads();

        if (c + NSTG - 1 < NCHUNK) {
            const int s = (c + NSTG - 1) % NSTG;
            const uint32_t aB = sbase + s * STAGE_BYTES;
            const size_t kk = (size_t)(c + NSTG - 1) * BK;
            #pragma unroll
            for (int r = 0; r < 8; ++r) {
                const int row = lrow + r * 16;
                const uint32_t off = SWZ(row * 128 + lch * 16);
                cp_async16(aB + off, g_Ebf + (size_t)(ib + row) * DD + kk + lch * 8);
            }
            if (!isdiag) {
                #pragma unroll
                for (int r = 0; r < 8; ++r) {
                    const int row = lrow + r * 16;
                    const uint32_t off = SWZ(row * 128 + lch * 16);
                    cp_async16(aB + TILE_KB + off,
                               g_Ebf + (size_t)(jb + row) * DD + kk + lch * 8);
                }
            }
        }
        cp_commit();

        const uint32_t aB = sbase + (c % NSTG) * STAGE_BYTES;
        const uint32_t bB = aB + bofs;
        #pragma unroll
        for (int kq = 0; kq < 4; ++kq) {   // 4 x k16
            uint32_t b[4][4];
            #pragma unroll
            for (int nq = 0; nq < 4; ++nq) {
                const int row = wn * 64 + nq * 16 + (lane & 7) + ((lane >> 4) << 3);
                const int byc = kq * 32 + ((lane >> 3) & 1) * 16;
                ldsm_x4(b[nq], bB + SWZ(row * 128 + byc));
            }
            #pragma unroll
            for (int mt = 0; mt < 4; ++mt) {
                uint32_t a[4];
                const int row = wm * 64 + mt * 16 + (lane & 15);
                const int byc = kq * 32 + (lane >> 4) * 16;
                ldsm_x4(a, aB + SWZ(row * 128 + byc));
                #pragma unroll
                for (int nt = 0; nt < 8; ++nt)
                    mma_bf16(acc[mt][nt], a,
                             b[nt >> 1][(nt & 1) * 2], b[nt >> 1][(nt & 1) * 2 + 1]);
            }
        }
    }
    __syncthreads();   // all reads done before epilogue reuses stage smem

    // ---------------- epilogue: exp sums + masked dot sums ----------------
    const int r_lo = (lane >> 2);
    const int c_lo = (lane & 3) * 2;

    float mi0[4], mi1[4];
    #pragma unroll
    for (int mt = 0; mt < 4; ++mt) {
        const int gi0 = ib + wm * 64 + mt * 16 + r_lo;
        mi0[mt] = g_mask[gi0];
        mi1[mt] = g_mask[gi0 + 8];
    }
    float mj0[8], mj1[8];
    #pragma unroll
    for (int nt = 0; nt < 8; ++nt) {
        const int gj0 = jb + wn * 64 + nt * 8 + c_lo;
        mj0[nt] = g_mask[gj0];
        mj1[nt] = g_mask[gj0 + 1];
    }

    float rowp[4][2], colp[8][2], rowd[4][2], cold[8][2];
    #pragma unroll
    for (int mt = 0; mt < 4; ++mt) {
        rowp[mt][0] = 0.f; rowp[mt][1] = 0.f;
        rowd[mt][0] = 0.f; rowd[mt][1] = 0.f;
    }
    #pragma unroll
    for (int nt = 0; nt < 8; ++nt) {
        colp[nt][0] = 0.f; colp[nt][1] = 0.f;
        cold[nt][0] = 0.f; cold[nt][1] = 0.f;
    }

    #pragma unroll
    for (int mt = 0; mt < 4; ++mt) {
        const int gi0 = ib + wm * 64 + mt * 16 + r_lo;
        const int gi1 = gi0 + 8;
        #pragma unroll
        for (int nt = 0; nt < 8; ++nt) {
            const int gj0 = jb + wn * 64 + nt * 8 + c_lo;
            const int gj1 = gj0 + 1;
            const float a00 = acc[mt][nt][0], a01 = acc[mt][nt][1];
            const float a10 = acc[mt][nt][2], a11 = acc[mt][nt][3];
            rowd[mt][0] += a00 * mj0[nt] + a01 * mj1[nt];
            rowd[mt][1] += a10 * mj0[nt] + a11 * mj1[nt];
            cold[nt][0] += a00 * mi0[mt] + a10 * mi1[mt];
            cold[nt][1] += a01 * mi0[mt] + a11 * mi1[mt];
            // exp(a/TEMP) = exp2(a * INV_TEMP_LOG2E): one FMUL + EX2 per element
            float e00 = exp2f(a00 * INV_TEMP_LOG2E);
            float e01 = exp2f(a01 * INV_TEMP_LOG2E);
            float e10 = exp2f(a10 * INV_TEMP_LOG2E);
            float e11 = exp2f(a11 * INV_TEMP_LOG2E);
            if (isdiag) {
                if (gi0 == gj0) e00 = 0.0f;
                if (gi0 == gj1) e01 = 0.0f;
                if (gi1 == gj0) e10 = 0.0f;
                if (gi1 == gj1) e11 = 0.0f;
            }
            rowp[mt][0] += e00 + e01;
            rowp[mt][1] += e10 + e11;
            colp[nt][0] += e00 + e10;
            colp[nt][1] += e01 + e11;
        }
    }

    #pragma unroll
    for (int mt = 0; mt < 4; ++mt)
        #pragma unroll
        for (int h = 0; h < 2; ++h) {
            float v = rowp[mt][h];
            v += __shfl_xor_sync(0xffffffffu, v, 1);
            v += __shfl_xor_sync(0xffffffffu, v, 2);
            rowp[mt][h] = v;
            float w = rowd[mt][h];
            w += __shfl_xor_sync(0xffffffffu, w, 1);
            w += __shfl_xor_sync(0xffffffffu, w, 2);
            rowd[mt][h] = w;
        }
    #pragma unroll
    for (int nt = 0; nt < 8; ++nt)
        #pragma unroll
        for (int j = 0; j < 2; ++j) {
            float v = colp[nt][j];
            v += __shfl_xor_sync(0xffffffffu, v, 4);
            v += __shfl_xor_sync(0xffffffffu, v, 8);
            v += __shfl_xor_sync(0xffffffffu, v, 16);
            colp[nt][j] = v;
            float w = cold[nt][j];
            w += __shfl_xor_sync(0xffffffffu, w, 4);
            w += __shfl_xor_sync(0xffffffffu, w, 8);
            w += __shfl_xor_sync(0xffffffffu, w, 16);
            cold[nt][j] = w;
        }

    float* rowred  = (float*)smem;               // [128][2]
    float* colred  = (float*)(smem + 1024);      // [128][2]
    float* rowdred = (float*)(smem + 2048);      // [128][2]
    float* coldred = (float*)(smem + 3072);      // [128][2]

    if ((lane & 3) == 0) {
        #pragma unroll
        for (int mt = 0; mt < 4; ++mt)
            #pragma unroll
            for (int h = 0; h < 2; ++h) {
                const int row = wm * 64 + mt * 16 + r_lo + 8 * h;
                rowred[row * 2 + wn]  = rowp[mt][h];
                rowdred[row * 2 + wn] = rowd[mt][h];
            }
    }
    if (lane < 4) {
        #pragma unroll
        for (int nt = 0; nt < 8; ++nt)
            #pragma unroll
            for (int j = 0; j < 2; ++j) {
                const int col = wn * 64 + nt * 8 + lane * 2 + j;
                colred[col * 2 + wm]  = colp[nt][j];
                coldred[col * 2 + wm] = cold[nt][j];
            }
    }
    __syncthreads();

    atomicAdd(&g_Z[ib + tid],    rowred[tid * 2]  + rowred[tid * 2 + 1]);
    atomicAdd(&g_dotM[ib + tid], rowdred[tid * 2] + rowdred[tid * 2 + 1]);
    if (!isdiag) {
        atomicAdd(&g_Z[jb + tid],    colred[tid * 2]  + colred[tid * 2 + 1]);
        atomicAdd(&g_dotM[jb + tid], coldred[tid * 2] + coldred[tid * 2 + 1]);
    }
}

// ======================= finalize (single kernel, last-block-done) ==============
// |Sp| <= 1/TEMP so exp(Sp) <= 1.6e6: fp32-safe, no max-subtraction.
// ||e_i||^2 == 1 exactly (unit-norm), so pos uses (dotM - 1).
#define FIN_BLOCKS (BB / 256)   // 32

__global__ void finalize_kernel(const int* __restrict__ labels,
                                const float* __restrict__ dist,
                                const float* __restrict__ rm_p,
                                const float* __restrict__ rh_p,
                                float* __restrict__ out) {
    const int i = blockIdx.x * 256 + threadIdx.x;
    const int t = threadIdx.x;

    const float sp = g_Sp[i];
    const float ep = __expf(sp);
    const bool m = (labels[i] == 0);
    const float d = dist[i];

    float lse = 0.0f, pos = 0.0f, msp = 0.0f, sm = 0.0f, sh2 = 0.0f;
    int cm = 0;
    if (m) {
        lse = __logf(g_Z[i] + ep);
        pos = (g_dotM[i] - 1.0f) * INV_TEMP + sp;
        msp = sp;
        cm = 1;
        float r = fmaxf(d - rm_p[0], 0.0f);
        sm = r * r;
    } else {
        float r = fmaxf(rh_p[0] - d, 0.0f);
        sh2 = r * r;
    }

    __shared__ float s[6][256];
    __shared__ int   si[256];
    s[0][t] = ep; s[1][t] = msp; s[2][t] = lse; s[3][t] = pos;
    s[4][t] = sm; s[5][t] = sh2; si[t] = cm;
    __syncthreads();
    for (int o = 128; o > 0; o >>= 1) {
        if (t < o) {
            s[0][t] += s[0][t + o]; s[1][t] += s[1][t + o];
            s[2][t] += s[2][t + o]; s[3][t] += s[3][t + o];
            s[4][t] += s[4][t + o]; s[5][t] += s[5][t + o];
            si[t] += si[t + o];
        }
        __syncthreads();
    }
    __shared__ int s_last;
    if (t == 0) {
        atomicAdd(&g_sumexp_p,  s[0][0]);
        atomicAdd(&g_sum_m_sp,  s[1][0]);
        atomicAdd(&g_sum_m_lse, s[2][0]);
        atomicAdd(&g_sum_m_pos, s[3][0]);
        atomicAdd(&g_shell_m,   s[4][0]);
        atomicAdd(&g_shell_h,   s[5][0]);
        atomicAdd(&g_nm,        si[0]);
        __threadfence();
        s_last = (atomicAdd(&g_done, 1) == FIN_BLOCKS - 1) ? 1 : 0;
    }
    __syncthreads();
    if (s_last && t == 0) {
        const int nm_i = g_nm;
        const int nh_i = BB - nm_i;
        const float nm_den = fmaxf((float)nm_i, 1.0f);
        const float nh_den = fmaxf((float)nh_i, 1.0f);

        float con_sum = g_sum_m_lse - g_sum_m_pos / nm_den;
        float lse_p = logf(g_sumexp_p);
        float proto_loss = lse_p - g_sum_m_sp / nm_den;
        float loss_con = (con_sum + proto_loss) / fmaxf((float)(nm_i + 1), 1.0f);
        if (!(nm_i > 0 && nh_i > 0)) loss_con = 0.0f;
        float loss_m = g_shell_m / nm_den;
        float loss_h = g_shell_h / nh_den;
        float loss_shell = loss_m + loss_h;
        out[0] = loss_shell + loss_con;
        out[1] = loss_shell;
        out[2] = loss_m;
        out[3] = loss_h;
        out[4] = loss_con;
    }
}

extern "C" void kernel_launch(void* const* d_in, const int* in_sizes, int n_in,
                              void* d_out, int out_size) {
    const float* E      = (const float*)d_in[0];
    const float* center = (const float*)d_in[1];
    const float* rm     = (const float*)d_in[2];
    const float* rh     = (const float*)d_in[3];
    const int*   labels = (const int*)d_in[4];
    float* out = (float*)d_out;

    const int dist_off = out_size - BB;

    cudaFuncSetAttribute(gemm_expsum_kernel,
                         cudaFuncAttributeMaxDynamicSharedMemorySize, SMEM_TOTAL);

    row_stats_kernel<<<BB / 8, 256>>>(E, center, labels, out, dist_off);
    gemm_expsum_kernel<<<(NTILE * (NTILE + 1)) / 2, 128, SMEM_TOTAL>>>();
    finalize_kernel<<<FIN_BLOCKS, 256>>>(labels, out + dist_off, rm, rh, out);
}